// round 8
// baseline (speedup 1.0000x reference)
#include <cuda_runtime.h>
#include <cstdint>

#define UNITS  512
#define NIN    256
#define NBATCH 512
#define JT 32          // j-columns per CTA
#define BT 16          // batches per CTA
#define NB 4           // batches per thread
#define NTHR 128
#define VSTR 20        // smem row stride (floats): float4-aligned, broadcast reads
#define CH 8           // prefetch chunk (param float4s in flight)
#define NTILE 512      // (UNITS/JT)*(NBATCH/BT) tiles per step

// ---------------- device scratch (static, no runtime allocation) -------------
__device__ float4 RPd[UNITS*UNITS];   // recurrent params {s, c, Wh, WEh}
__device__ float4 SPd[NIN*UNITS];     // sensory params
__device__ float2 QP0[NBATCH*UNITS];  // partial (num,den), i-half 0
__device__ float2 QP1[NBATCH*UNITS];  // partial (num,den), i-half 1
__device__ float  NSd[NBATCH*UNITS];  // sensory numerator term [b][j]
__device__ float  DSd[NBATCH*UNITS];  // sensory denominator term [b][j]
__device__ float  VBa[NBATCH*UNITS];  // v ping  [b][u]
__device__ float  VBb[NBATCH*UNITS];  // v pong  [b][u]
__device__ float  CGc_[UNITS];        // cm + gleak + sum_i Wh   (recurrent)
__device__ float  CNc_[UNITS];        // gleak*vleak + sum_i WEh (recurrent)
__device__ float  SWs_[UNITS];        // sum_i Wh   (sensory)
__device__ float  SWEs_[UNITS];       // sum_i WEh  (sensory)
__device__ unsigned int Ctr[7*NTILE]; // arrival counters: step 0 = sensory, 1..6 unfolds

// sigmoid(sigma*(v-mu)) = 0.5 + 0.5*tanh(0.5*sigma*v - 0.5*sigma*mu)
// act = W*sigmoid = Wh*tanh(u) + Wh with Wh = 0.5*W; constant "+Wh" halves are
// folded into per-j column sums applied once in the winner's combine epilogue.

// merged prep: transforms both param sets and zeroes the arrival counters
__global__ __launch_bounds__(256) void prep_all(
        const float* __restrict__ rmu, const float* __restrict__ rsg,
        const float* __restrict__ rW,  const float* __restrict__ rer,
        const float* __restrict__ smu, const float* __restrict__ ssg,
        const float* __restrict__ sW,  const float* __restrict__ ser) {
    int idx = blockIdx.x*blockDim.x + threadIdx.x;
    if (idx < UNITS*UNITS) {
        float s = rsg[idx], m = rmu[idx], w = rW[idx], e = rer[idx];
        RPd[idx] = make_float4(0.5f*s, -0.5f*s*m, 0.5f*w, 0.5f*w*e);
    }
    if (idx < NIN*UNITS) {
        float s = ssg[idx], m = smu[idx], w = sW[idx], e = ser[idx];
        SPd[idx] = make_float4(0.5f*s, -0.5f*s*m, 0.5f*w, 0.5f*w*e);
    }
    if (idx < 7*NTILE) Ctr[idx] = 0u;
}

// coalesced column sums: lane = j, 8 i-rows per warp-row, smem reduce
__global__ __launch_bounds__(256) void colsums(const float* __restrict__ cm,
                                               const float* __restrict__ gl,
                                               const float* __restrict__ vl) {
    __shared__ float sm[8][32][4];
    int tx = threadIdx.x & 31;
    int ty = threadIdx.x >> 5;
    int j  = blockIdx.x*32 + tx;

    float rw = 0.f, rwe = 0.f, sw = 0.f, swe = 0.f;
    for (int i = ty; i < UNITS; i += 8) { float4 p = RPd[i*UNITS + j]; rw += p.z; rwe += p.w; }
    for (int i = ty; i < NIN;   i += 8) { float4 p = SPd[i*UNITS + j]; sw += p.z; swe += p.w; }
    sm[ty][tx][0] = rw; sm[ty][tx][1] = rwe; sm[ty][tx][2] = sw; sm[ty][tx][3] = swe;
    __syncthreads();
    if (ty == 0) {
        for (int r = 1; r < 8; r++) {
            rw += sm[r][tx][0]; rwe += sm[r][tx][1];
            sw += sm[r][tx][2]; swe += sm[r][tx][3];
        }
        SWs_[j]  = sw;
        SWEs_[j] = swe;
        CGc_[j]  = cm[j] + gl[j] + rw;
        CNc_[j]  = gl[j]*vl[j] + rwe;
    }
}

__device__ __forceinline__ float tanh_apx(float x) {
    float y;
    asm("tanh.approx.f32 %0, %1;" : "=f"(y) : "f"(x));
    return y;
}

// ---------------- sensory partials + winner combine ---------------------------
__global__ __launch_bounds__(NTHR) void sensory_k(const float* __restrict__ inp,
                                                  const float* __restrict__ iw,
                                                  const float* __restrict__ ib) {
    __shared__ float xs[(NIN/2)*VSTR];   // 10 KB
    __shared__ unsigned int who;
    const int IH = NIN/2;                // 128
    int jbase = blockIdx.x * JT;
    int bbase = blockIdx.y * BT;
    int ih    = blockIdx.z;              // 0 or 1
    int tile  = blockIdx.y*gridDim.x + blockIdx.x;
    int t = threadIdx.x;

    // stage x = inputs*input_w + input_b, transposed: xs[il*VSTR + b]
    for (int idx = t; idx < BT*IH; idx += NTHR) {
        int b  = idx >> 7;               // IH = 128
        int il = idx & (IH-1);
        int i  = ih*IH + il;
        xs[il*VSTR + b] = fmaf(inp[(bbase + b)*NIN + i], iw[i], ib[i]);
    }
    __syncthreads();

    int tx = t & 31;
    int bg = t >> 5;                     // warp-uniform
    int j  = jbase + tx;

    const float4* __restrict__ rp = SPd + (size_t)ih*IH*UNITS + j;
    float num0=0.f,num1=0.f,num2=0.f,num3=0.f;
    float den0=0.f,den1=0.f,den2=0.f,den3=0.f;

    float4 PA[CH], PB[CH];
    #pragma unroll
    for (int k = 0; k < CH; k++) PA[k] = rp[(size_t)k*UNITS];

    const int NC = IH/CH;                // 16 chunks
    #pragma unroll 1
    for (int c = 0; c < NC; c += 2) {
        { const float4* q = rp + (size_t)(c+1)*CH*UNITS;
          #pragma unroll
          for (int k = 0; k < CH; k++) PB[k] = q[(size_t)k*UNITS]; }
        #pragma unroll
        for (int k = 0; k < CH; k++) {
            float4 p  = PA[k];
            float4 vv = *reinterpret_cast<const float4*>(xs + (c*CH + k)*VSTR + bg*NB);
            float h0 = tanh_apx(fmaf(p.x, vv.x, p.y));
            float h1 = tanh_apx(fmaf(p.x, vv.y, p.y));
            float h2 = tanh_apx(fmaf(p.x, vv.z, p.y));
            float h3 = tanh_apx(fmaf(p.x, vv.w, p.y));
            den0 = fmaf(p.z, h0, den0); num0 = fmaf(p.w, h0, num0);
            den1 = fmaf(p.z, h1, den1); num1 = fmaf(p.w, h1, num1);
            den2 = fmaf(p.z, h2, den2); num2 = fmaf(p.w, h2, num2);
            den3 = fmaf(p.z, h3, den3); num3 = fmaf(p.w, h3, num3);
        }
        { int cn = (c + 2 < NC) ? (c + 2) : 0;
          const float4* q = rp + (size_t)cn*CH*UNITS;
          #pragma unroll
          for (int k = 0; k < CH; k++) PA[k] = q[(size_t)k*UNITS]; }
        #pragma unroll
        for (int k = 0; k < CH; k++) {
            float4 p  = PB[k];
            float4 vv = *reinterpret_cast<const float4*>(xs + ((c+1)*CH + k)*VSTR + bg*NB);
            float h0 = tanh_apx(fmaf(p.x, vv.x, p.y));
            float h1 = tanh_apx(fmaf(p.x, vv.y, p.y));
            float h2 = tanh_apx(fmaf(p.x, vv.z, p.y));
            float h3 = tanh_apx(fmaf(p.x, vv.w, p.y));
            den0 = fmaf(p.z, h0, den0); num0 = fmaf(p.w, h0, num0);
            den1 = fmaf(p.z, h1, den1); num1 = fmaf(p.w, h1, num1);
            den2 = fmaf(p.z, h2, den2); num2 = fmaf(p.w, h2, num2);
            den3 = fmaf(p.z, h3, den3); num3 = fmaf(p.w, h3, num3);
        }
    }

    float2* __restrict__ pp = (ih == 0) ? QP0 : QP1;
    float nn[NB] = {num0,num1,num2,num3};
    float dd[NB] = {den0,den1,den2,den3};
    #pragma unroll
    for (int k = 0; k < NB; k++) {
        int b = bbase + bg*NB + k;
        pp[b*UNITS + j] = make_float2(nn[k], dd[k]);
    }

    // last-arriver combines partials into NSd/DSd (fixed z-order: deterministic)
    __threadfence();
    if (t == 0) who = atomicAdd(&Ctr[tile], 1u);
    __syncthreads();
    if (who == 1u) {
        __threadfence();
        float swe = SWEs_[j], sw = SWs_[j];
        #pragma unroll
        for (int k = 0; k < NB; k++) {
            int g = (bbase + bg*NB + k)*UNITS + j;
            float2 a = QP0[g];
            float2 c = QP1[g];
            NSd[g] = a.x + c.x + swe;
            DSd[g] = a.y + c.y + sw;
        }
    }
}

// ---------------- unfold partials + winner combine (writes v or d_out) --------
__global__ __launch_bounds__(NTHR) void unfold_k(const float* __restrict__ vext,
                                                 const float* __restrict__ cm,
                                                 float* __restrict__ dout,
                                                 int in_sel, int out_sel, int step) {
    __shared__ float vs[(UNITS/2)*VSTR];  // 20 KB
    __shared__ unsigned int who;
    const int IH = UNITS/2;               // 256
    const float* vin  = (in_sel  == 0) ? vext : (in_sel  == 1 ? VBa : VBb);
    float*       vout = (out_sel == 0) ? dout : (out_sel == 1 ? VBa : VBb);

    int jbase = blockIdx.x * JT;
    int bbase = blockIdx.y * BT;
    int ih    = blockIdx.z;
    int tile  = blockIdx.y*gridDim.x + blockIdx.x;
    int t = threadIdx.x;

    // stage v transposed: vs[il*VSTR + b]
    for (int idx = t; idx < BT*IH; idx += NTHR) {
        int b  = idx >> 8;                // IH = 256
        int il = idx & (IH-1);
        vs[il*VSTR + b] = vin[(bbase + b)*UNITS + ih*IH + il];
    }
    __syncthreads();

    int tx = t & 31;
    int bg = t >> 5;
    int j  = jbase + tx;

    const float4* __restrict__ rp = RPd + (size_t)ih*IH*UNITS + j;
    float num0=0.f,num1=0.f,num2=0.f,num3=0.f;
    float den0=0.f,den1=0.f,den2=0.f,den3=0.f;

    float4 PA[CH], PB[CH];
    #pragma unroll
    for (int k = 0; k < CH; k++) PA[k] = rp[(size_t)k*UNITS];

    const int NC = IH/CH;                 // 32 chunks
    #pragma unroll 1
    for (int c = 0; c < NC; c += 2) {
        { const float4* q = rp + (size_t)(c+1)*CH*UNITS;
          #pragma unroll
          for (int k = 0; k < CH; k++) PB[k] = q[(size_t)k*UNITS]; }
        #pragma unroll
        for (int k = 0; k < CH; k++) {
            float4 p  = PA[k];
            float4 vv = *reinterpret_cast<const float4*>(vs + (c*CH + k)*VSTR + bg*NB);
            float h0 = tanh_apx(fmaf(p.x, vv.x, p.y));
            float h1 = tanh_apx(fmaf(p.x, vv.y, p.y));
            float h2 = tanh_apx(fmaf(p.x, vv.z, p.y));
            float h3 = tanh_apx(fmaf(p.x, vv.w, p.y));
            den0 = fmaf(p.z, h0, den0); num0 = fmaf(p.w, h0, num0);
            den1 = fmaf(p.z, h1, den1); num1 = fmaf(p.w, h1, num1);
            den2 = fmaf(p.z, h2, den2); num2 = fmaf(p.w, h2, num2);
            den3 = fmaf(p.z, h3, den3); num3 = fmaf(p.w, h3, num3);
        }
        { int cn = (c + 2 < NC) ? (c + 2) : 0;
          const float4* q = rp + (size_t)cn*CH*UNITS;
          #pragma unroll
          for (int k = 0; k < CH; k++) PA[k] = q[(size_t)k*UNITS]; }
        #pragma unroll
        for (int k = 0; k < CH; k++) {
            float4 p  = PB[k];
            float4 vv = *reinterpret_cast<const float4*>(vs + ((c+1)*CH + k)*VSTR + bg*NB);
            float h0 = tanh_apx(fmaf(p.x, vv.x, p.y));
            float h1 = tanh_apx(fmaf(p.x, vv.y, p.y));
            float h2 = tanh_apx(fmaf(p.x, vv.z, p.y));
            float h3 = tanh_apx(fmaf(p.x, vv.w, p.y));
            den0 = fmaf(p.z, h0, den0); num0 = fmaf(p.w, h0, num0);
            den1 = fmaf(p.z, h1, den1); num1 = fmaf(p.w, h1, num1);
            den2 = fmaf(p.z, h2, den2); num2 = fmaf(p.w, h2, num2);
            den3 = fmaf(p.z, h3, den3); num3 = fmaf(p.w, h3, num3);
        }
    }

    float2* __restrict__ pp = (ih == 0) ? QP0 : QP1;
    float nn[NB] = {num0,num1,num2,num3};
    float dd[NB] = {den0,den1,den2,den3};
    #pragma unroll
    for (int k = 0; k < NB; k++) {
        int b = bbase + bg*NB + k;
        pp[b*UNITS + j] = make_float2(nn[k], dd[k]);
    }

    // last-arriver combines both halves and writes v (fixed z-order: deterministic)
    __threadfence();
    if (t == 0) who = atomicAdd(&Ctr[step*NTILE + tile], 1u);
    __syncthreads();
    if (who == 1u) {
        __threadfence();
        float cgj = CGc_[j], cnj = CNc_[j], cmj = cm[j];
        #pragma unroll
        for (int k = 0; k < NB; k++) {
            int g = (bbase + bg*NB + k)*UNITS + j;
            float2 a = QP0[g];
            float2 c = QP1[g];
            float vp = vin[g];
            float numer = fmaf(cmj, vp, cnj + NSd[g] + a.x + c.x);
            float denom = cgj + DSd[g] + a.y + c.y;
            vout[g] = __fdividef(numer, denom);
        }
    }
}

// ---------------- launch ------------------------------------------------------
extern "C" void kernel_launch(void* const* d_in, const int* in_sizes, int n_in,
                              void* d_out, int out_size) {
    const float* inputs = (const float*)d_in[0];
    const float* state  = (const float*)d_in[1];
    const float* iw     = (const float*)d_in[2];
    const float* ib     = (const float*)d_in[3];
    const float* smu    = (const float*)d_in[4];
    const float* ssig   = (const float*)d_in[5];
    const float* sW     = (const float*)d_in[6];
    const float* serev  = (const float*)d_in[7];
    const float* rmu    = (const float*)d_in[8];
    const float* rsig   = (const float*)d_in[9];
    const float* rW     = (const float*)d_in[10];
    const float* rerev  = (const float*)d_in[11];
    const float* vleak  = (const float*)d_in[12];
    const float* gleak  = (const float*)d_in[13];
    const float* cm     = (const float*)d_in[14];
    float* out = (float*)d_out;

    prep_all<<<(UNITS*UNITS + 255)/256, 256>>>(rmu, rsig, rW, rerev,
                                               smu, ssig, sW, serev);
    colsums<<<UNITS/32, 256>>>(cm, gleak, vleak);

    dim3 grid(UNITS/JT, NBATCH/BT, 2);   // 16 x 32 x 2 = 1024 CTAs
    sensory_k<<<grid, NTHR>>>(inputs, iw, ib);

    // 6 unfolds: state -> VBa -> VBb -> VBa -> VBb -> VBa -> d_out
    unfold_k<<<grid, NTHR>>>(state,   cm, nullptr, 0, 1, 1);
    unfold_k<<<grid, NTHR>>>(nullptr, cm, nullptr, 1, 2, 2);
    unfold_k<<<grid, NTHR>>>(nullptr, cm, nullptr, 2, 1, 3);
    unfold_k<<<grid, NTHR>>>(nullptr, cm, nullptr, 1, 2, 4);
    unfold_k<<<grid, NTHR>>>(nullptr, cm, nullptr, 2, 1, 5);
    unfold_k<<<grid, NTHR>>>(nullptr, cm, out,     1, 0, 6);
}